// round 16
// baseline (speedup 1.0000x reference)
#include <cuda_runtime.h>
#include <cstddef>
#include <cstdint>

// Fixed problem shape: bs=32, V=65536, F=130050, C=6.  BS == warp size.
#define BS 32
#define NV 65536
#define NF 130050
#define NC 6

#define QSCALE 32766.0f            // fn snorm16 encode
#define QINV   (1.0f / 32766.0f)

// Scratch (device globals), batch-innermost:
__device__ float2 g_ptsXY[(size_t)NV * BS];
__device__ float  g_ptsZ[(size_t)NV * BS];
__device__ short4 g_fn4[(size_t)NF * BS];

// ---------------------------------------------------------------------------
// Kernel 1: transpose points (BS,3,V) -> split planes (R11 config, 11.9us).
// ---------------------------------------------------------------------------
#define TV 64
__global__ void __launch_bounds__(256)
transpose_kernel(const float* __restrict__ points)
{
    __shared__ float s[3][TV][33];          // [c][v_in_tile][b], 25.3 KB
    int v0 = blockIdx.x * TV;
    int t  = threadIdx.x;

    // Phase 1: 96 rows (b*3+c) x 16 float4 = 1536 vector loads; 6 per thread.
#pragma unroll
    for (int k = 0; k < 6; k++) {
        int idx  = t + k * 256;             // 0..1535
        int row  = idx >> 4;                // 0..95 = b*3 + c
        int col4 = idx & 15;
        int b    = row / 3;
        int c    = row - 3 * b;
        float4 p = *(const float4*)&points[(size_t)row * NV + v0 + col4 * 4];
        int vj = col4 * 4;
        s[c][vj + 0][b] = p.x;
        s[c][vj + 1][b] = p.y;
        s[c][vj + 2][b] = p.z;
        s[c][vj + 3][b] = p.w;
    }
    __syncthreads();

    // Phase 2: 8 warps x 8 rows; conflict-free LDS; 1 STG.64 + 1 STG.32.
    int lane = t & 31;
    int wid  = t >> 5;
#pragma unroll
    for (int r = wid; r < TV; r += 8) {
        size_t o = (size_t)(v0 + r) * BS + lane;
        g_ptsXY[o] = make_float2(s[0][r][lane], s[1][r][lane]);
        g_ptsZ[o]  = s[2][r][lane];
    }

#if __CUDA_ARCH__ >= 900
    cudaTriggerProgrammaticLaunchCompletion();
#endif
}

// ---------------------------------------------------------------------------
// Kernel 2: face normals.  warp = 2 faces, lane = batch.  12 gathers (MLP=12).
// ---------------------------------------------------------------------------
__global__ void __launch_bounds__(256)
face_normals_kernel(const int* __restrict__ faces)
{
    int w    = (blockIdx.x * 256 + threadIdx.x) >> 5;  // warp id
    int lane = threadIdx.x & 31;                       // = batch
    int f0   = 2 * w;
    bool act = (f0 < NF);                              // NF even -> f0+1 valid

    // Prologue (independent of K1): 6 indices via 3x int2.
    int2 ia = make_int2(0, 0), ib = ia, ic = ia;
    if (act) {
        const int2* fr = (const int2*)(faces + 3 * f0);
        ia = __ldg(&fr[0]);
        ib = __ldg(&fr[1]);
        ic = __ldg(&fr[2]);
    }

#if __CUDA_ARCH__ >= 900
    cudaGridDependencySynchronize();
#endif
    if (!act) return;

    size_t o0 = (size_t)ia.x * BS + lane;
    size_t o1 = (size_t)ia.y * BS + lane;
    size_t o2 = (size_t)ib.x * BS + lane;
    size_t o3 = (size_t)ib.y * BS + lane;
    size_t o4 = (size_t)ic.x * BS + lane;
    size_t o5 = (size_t)ic.y * BS + lane;

    float2 u0 = g_ptsXY[o0];  float z0 = g_ptsZ[o0];
    float2 u1 = g_ptsXY[o1];  float z1 = g_ptsZ[o1];
    float2 u2 = g_ptsXY[o2];  float z2 = g_ptsZ[o2];
    float2 u3 = g_ptsXY[o3];  float z3 = g_ptsZ[o3];
    float2 u4 = g_ptsXY[o4];  float z4 = g_ptsZ[o4];
    float2 u5 = g_ptsXY[o5];  float z5 = g_ptsZ[o5];

    {
        float ax = u1.x - u0.x, ay = u1.y - u0.y, az = z1 - z0;
        float bx = u2.x - u0.x, by = u2.y - u0.y, bz = z2 - z0;
        float cx = ay * bz - az * by;
        float cy = az * bx - ax * bz;
        float cz = ax * by - ay * bx;
        float inv = QSCALE * rsqrtf(fmaxf(cx*cx + cy*cy + cz*cz, 1e-24f));
        g_fn4[(size_t)f0 * BS + lane] =
            make_short4((short)__float2int_rn(cx * inv),
                        (short)__float2int_rn(cy * inv),
                        (short)__float2int_rn(cz * inv), 0);
    }
    {
        float ax = u4.x - u3.x, ay = u4.y - u3.y, az = z4 - z3;
        float bx = u5.x - u3.x, by = u5.y - u3.y, bz = z5 - z3;
        float cx = ay * bz - az * by;
        float cy = az * bx - ax * bz;
        float cz = ax * by - ay * bx;
        float inv = QSCALE * rsqrtf(fmaxf(cx*cx + cy*cy + cz*cz, 1e-24f));
        g_fn4[(size_t)(f0 + 1) * BS + lane] =
            make_short4((short)__float2int_rn(cx * inv),
                        (short)__float2int_rn(cy * inv),
                        (short)__float2int_rn(cz * inv), 0);
    }

#if __CUDA_ARCH__ >= 900
    cudaTriggerProgrammaticLaunchCompletion();
#endif
}

// ---------------------------------------------------------------------------
// Kernel 3: vertex normals.  warp = 4 vertices, lane = batch.  MLP = 24.
// ---------------------------------------------------------------------------
__global__ void __launch_bounds__(256)
vertex_normals_kernel(const int*   __restrict__ vti,   // (V, C)
                      const float* __restrict__ vtw,   // (V, C)
                      float*       __restrict__ out)   // (BS, V, 3)
{
    __shared__ float so[32][33][3];         // [v_in_block][b][xyz], 12.6 KB

    int wid  = threadIdx.x >> 5;            // 0..7
    int lane = threadIdx.x & 31;            // = batch
    int bv0  = blockIdx.x * 32;             // block's first vertex
    int v    = bv0 + wid * 4;               // this warp: v..v+3

    // Prologue (independent of K2): uniform index/weight loads.
    int   f[4 * NC];
    float wgt[4 * NC];
#pragma unroll
    for (int h = 0; h < 4; h++) {
        const int2*   vti2 = (const int2*)(vti + (v + h) * NC);
        const float2* vtw2 = (const float2*)(vtw + (v + h) * NC);
#pragma unroll
        for (int c = 0; c < 3; c++) {
            int2   fi = __ldg(&vti2[c]);
            float2 wi = __ldg(&vtw2[c]);
            f[h * NC + 2 * c + 0]   = fi.x;
            f[h * NC + 2 * c + 1]   = fi.y;
            wgt[h * NC + 2 * c + 0] = wi.x * QINV;
            wgt[h * NC + 2 * c + 1] = wi.y * QINV;
        }
    }

#if __CUDA_ARCH__ >= 900
    cudaGridDependencySynchronize();
#endif

    // 24 independent gathers.
    short4 n[4 * NC];
#pragma unroll
    for (int c = 0; c < 4 * NC; c++)
        n[c] = g_fn4[(size_t)f[c] * BS + lane];

#pragma unroll
    for (int h = 0; h < 4; h++) {
        float ax = 0.0f, ay = 0.0f, az = 0.0f;
#pragma unroll
        for (int c = 0; c < NC; c++) {
            int i = h * NC + c;
            ax = fmaf((float)n[i].x, wgt[i], ax);
            ay = fmaf((float)n[i].y, wgt[i], ay);
            az = fmaf((float)n[i].z, wgt[i], az);
        }
        float inv = rsqrtf(fmaxf(ax*ax + ay*ay + az*az, 1e-24f));
        so[wid * 4 + h][lane][0] = ax * inv;
        so[wid * 4 + h][lane][1] = ay * inv;
        so[wid * 4 + h][lane][2] = az * inv;
    }
    __syncthreads();

    // Write out (b, v, 3): 4 rounds of 8 vertices; 12B contiguous per thread.
    int b = threadIdx.x >> 3;
    int j = threadIdx.x & 7;
#pragma unroll
    for (int h = 0; h < 4; h++) {
        size_t o = ((size_t)b * NV + (bv0 + h * 8 + j)) * 3;
        out[o + 0] = so[h * 8 + j][b][0];
        out[o + 1] = so[h * 8 + j][b][1];
        out[o + 2] = so[h * 8 + j][b][2];
    }
}

// ---------------------------------------------------------------------------
extern "C" void kernel_launch(void* const* d_in, const int* in_sizes, int n_in,
                              void* d_out, int out_size)
{
    const float* points = (const float*)d_in[0];  // (BS, 3, V)
    const int*   faces  = (const int*)  d_in[1];  // (F, 3)
    const int*   vti    = (const int*)  d_in[2];  // (V, C)
    const float* vtw    = (const float*)d_in[3];  // (V, C, 1)
    float*       out    = (float*)d_out;          // (BS, V, 3)

    // K1: normal launch.
    transpose_kernel<<<NV / TV, 256>>>(points);

    // K2, K3: programmatic dependent launches (PDL).
    cudaLaunchAttribute attr[1];
    attr[0].id = cudaLaunchAttributeProgrammaticStreamSerialization;
    attr[0].val.programmaticStreamSerializationAllowed = 1;

    {
        int warps  = NF / 2;                // 65025
        int blocks = (warps + 7) / 8;       // 8 warps per block
        cudaLaunchConfig_t cfg = {};
        cfg.gridDim  = dim3(blocks);
        cfg.blockDim = dim3(256);
        cfg.attrs    = attr;
        cfg.numAttrs = 1;
        cudaLaunchKernelEx(&cfg, face_normals_kernel, faces);
    }
    {
        cudaLaunchConfig_t cfg = {};
        cfg.gridDim  = dim3(NV / 32);       // 2048 blocks, 4 verts/warp
        cfg.blockDim = dim3(256);
        cfg.attrs    = attr;
        cfg.numAttrs = 1;
        cudaLaunchKernelEx(&cfg, vertex_normals_kernel, vti, vtw, out);
    }
}

// round 17
// speedup vs baseline: 1.0944x; 1.0944x over previous
#include <cuda_runtime.h>
#include <cstddef>
#include <cstdint>

// Fixed problem shape: bs=32, V=65536, F=130050, C=6.  BS == warp size.
#define BS 32
#define NV 65536
#define NF 130050
#define NC 6

#define QSCALE 32766.0f            // fn snorm16 encode
#define QINV   (1.0f / 32766.0f)

// Scratch (device globals), batch-innermost:
__device__ float2 g_ptsXY[(size_t)NV * BS];
__device__ float  g_ptsZ[(size_t)NV * BS];
__device__ short4 g_fn4[(size_t)NF * BS];

__device__ __forceinline__ uint32_t smem_u32(const void* p) {
    uint32_t a;
    asm("{ .reg .u64 t; cvta.to.shared.u64 t, %1; cvt.u32.u64 %0, t; }"
        : "=r"(a) : "l"(p));
    return a;
}

// ---------------------------------------------------------------------------
// Kernel 1: transpose points (BS,3,V) -> split planes (R14 config, 12.0us).
// Pipelined: 4 tiles per CTA, double-buffered cp.async.
// ---------------------------------------------------------------------------
#define TV 64
#define ROWW 65
#define NTILE 4
#define BUFW (96 * ROWW)           // words per buffer
__global__ void __launch_bounds__(256)
transpose_kernel(const float* __restrict__ points)
{
    extern __shared__ float s[];            // [2][96][ROWW]
    int t     = threadIdx.x;
    int col   = t & 63;
    int rbase = t >> 6;                     // 0..3
    int tile0 = blockIdx.x * NTILE;
    int lane  = t & 31;
    int wid   = t >> 5;

    uint32_t sbase = smem_u32(s);

    auto issue = [&](int buf, int tile) {
        int v0 = tile * TV;
        uint32_t sb = sbase + (uint32_t)(buf * BUFW) * 4u;
#pragma unroll
        for (int k = 0; k < 24; k++) {
            int row = 4 * k + rbase;        // 0..95 = b*3 + c
            const float* gp = &points[(size_t)row * NV + v0 + col];
            uint32_t sp = sb + (uint32_t)(row * ROWW + col) * 4u;
            asm volatile("cp.async.ca.shared.global [%0], [%1], 4;"
                         :: "r"(sp), "l"(gp));
        }
        asm volatile("cp.async.commit_group;");
    };

    issue(0, tile0);
#pragma unroll
    for (int i = 0; i < NTILE; i++) {
        if (i + 1 < NTILE) {
            issue((i + 1) & 1, tile0 + i + 1);
            asm volatile("cp.async.wait_group 1;");
        } else {
            asm volatile("cp.async.wait_group 0;");
        }
        __syncthreads();

        int v0 = (tile0 + i) * TV;
        const float* sb = s + (i & 1) * BUFW;
#pragma unroll
        for (int r = wid; r < TV; r += 8) {
            float x = sb[(3 * lane + 0) * ROWW + r];
            float y = sb[(3 * lane + 1) * ROWW + r];
            float z = sb[(3 * lane + 2) * ROWW + r];
            size_t o = (size_t)(v0 + r) * BS + lane;
            g_ptsXY[o] = make_float2(x, y);
            g_ptsZ[o]  = z;
        }
        __syncthreads();
    }

#if __CUDA_ARCH__ >= 900
    cudaTriggerProgrammaticLaunchCompletion();
#endif
}

// ---------------------------------------------------------------------------
// Kernel 2: face normals.  warp = 2 faces, lane = batch.  12 gathers (MLP=12).
// ---------------------------------------------------------------------------
__global__ void __launch_bounds__(256)
face_normals_kernel(const int* __restrict__ faces)
{
    int w    = (blockIdx.x * 256 + threadIdx.x) >> 5;  // warp id
    int lane = threadIdx.x & 31;                       // = batch
    int f0   = 2 * w;
    bool act = (f0 < NF);                              // NF even -> f0+1 valid

    int2 ia = make_int2(0, 0), ib = ia, ic = ia;
    if (act) {
        const int2* fr = (const int2*)(faces + 3 * f0);
        ia = __ldg(&fr[0]);
        ib = __ldg(&fr[1]);
        ic = __ldg(&fr[2]);
    }

#if __CUDA_ARCH__ >= 900
    cudaGridDependencySynchronize();
#endif
    if (!act) return;

    size_t o0 = (size_t)ia.x * BS + lane;
    size_t o1 = (size_t)ia.y * BS + lane;
    size_t o2 = (size_t)ib.x * BS + lane;
    size_t o3 = (size_t)ib.y * BS + lane;
    size_t o4 = (size_t)ic.x * BS + lane;
    size_t o5 = (size_t)ic.y * BS + lane;

    float2 u0 = g_ptsXY[o0];  float z0 = g_ptsZ[o0];
    float2 u1 = g_ptsXY[o1];  float z1 = g_ptsZ[o1];
    float2 u2 = g_ptsXY[o2];  float z2 = g_ptsZ[o2];
    float2 u3 = g_ptsXY[o3];  float z3 = g_ptsZ[o3];
    float2 u4 = g_ptsXY[o4];  float z4 = g_ptsZ[o4];
    float2 u5 = g_ptsXY[o5];  float z5 = g_ptsZ[o5];

    {
        float ax = u1.x - u0.x, ay = u1.y - u0.y, az = z1 - z0;
        float bx = u2.x - u0.x, by = u2.y - u0.y, bz = z2 - z0;
        float cx = ay * bz - az * by;
        float cy = az * bx - ax * bz;
        float cz = ax * by - ay * bx;
        float inv = QSCALE * rsqrtf(fmaxf(cx*cx + cy*cy + cz*cz, 1e-24f));
        g_fn4[(size_t)f0 * BS + lane] =
            make_short4((short)__float2int_rn(cx * inv),
                        (short)__float2int_rn(cy * inv),
                        (short)__float2int_rn(cz * inv), 0);
    }
    {
        float ax = u4.x - u3.x, ay = u4.y - u3.y, az = z4 - z3;
        float bx = u5.x - u3.x, by = u5.y - u3.y, bz = z5 - z3;
        float cx = ay * bz - az * by;
        float cy = az * bx - ax * bz;
        float cz = ax * by - ay * bx;
        float inv = QSCALE * rsqrtf(fmaxf(cx*cx + cy*cy + cz*cz, 1e-24f));
        g_fn4[(size_t)(f0 + 1) * BS + lane] =
            make_short4((short)__float2int_rn(cx * inv),
                        (short)__float2int_rn(cy * inv),
                        (short)__float2int_rn(cz * inv), 0);
    }

#if __CUDA_ARCH__ >= 900
    cudaTriggerProgrammaticLaunchCompletion();
#endif
}

// ---------------------------------------------------------------------------
// Kernel 3: vertex normals.  warp = 2 vertices, lane = batch.  MLP = 12.
// Output via float4 stores: 384 STG.128 per block (was 1536 STG.32).
// ---------------------------------------------------------------------------
__global__ void __launch_bounds__(256)
vertex_normals_kernel(const int*   __restrict__ vti,   // (V, C)
                      const float* __restrict__ vtw,   // (V, C)
                      float*       __restrict__ out)   // (BS, V, 3)
{
    __shared__ float so[16][33][3];         // [v_in_block][b][xyz]

    int wid  = threadIdx.x >> 5;            // 0..7
    int lane = threadIdx.x & 31;            // = batch
    int bv0  = blockIdx.x * 16;             // block's first vertex
    int v    = bv0 + wid * 2;               // this warp: v, v+1

    // Prologue (independent of K2): uniform index/weight loads.
    int   f[2 * NC];
    float wgt[2 * NC];
#pragma unroll
    for (int h = 0; h < 2; h++) {
        const int2*   vti2 = (const int2*)(vti + (v + h) * NC);
        const float2* vtw2 = (const float2*)(vtw + (v + h) * NC);
#pragma unroll
        for (int c = 0; c < 3; c++) {
            int2   fi = __ldg(&vti2[c]);
            float2 wi = __ldg(&vtw2[c]);
            f[h * NC + 2 * c + 0]   = fi.x;
            f[h * NC + 2 * c + 1]   = fi.y;
            wgt[h * NC + 2 * c + 0] = wi.x * QINV;
            wgt[h * NC + 2 * c + 1] = wi.y * QINV;
        }
    }

#if __CUDA_ARCH__ >= 900
    cudaGridDependencySynchronize();
#endif

    // 12 independent gathers.
    short4 n[2 * NC];
#pragma unroll
    for (int c = 0; c < 2 * NC; c++)
        n[c] = g_fn4[(size_t)f[c] * BS + lane];

#pragma unroll
    for (int h = 0; h < 2; h++) {
        float ax = 0.0f, ay = 0.0f, az = 0.0f;
#pragma unroll
        for (int c = 0; c < NC; c++) {
            int i = h * NC + c;
            ax = fmaf((float)n[i].x, wgt[i], ax);
            ay = fmaf((float)n[i].y, wgt[i], ay);
            az = fmaf((float)n[i].z, wgt[i], az);
        }
        float inv = rsqrtf(fmaxf(ax*ax + ay*ay + az*az, 1e-24f));
        so[wid * 2 + h][lane][0] = ax * inv;
        so[wid * 2 + h][lane][1] = ay * inv;
        so[wid * 2 + h][lane][2] = az * inv;
    }
    __syncthreads();

    // Output: 16 verts x 32 batches x 3 floats = 384 float4s per block.
    // Float4 q (q = 0..383): b = q/12, k = q%12; covers floats 4k..4k+3 of
    // batch b's 48-float contiguous segment at out[(b*NV + bv0)*3].
    // Base (b*NV+bv0)*12 bytes*? -> (b*NV+bv0)*3 floats; *4B: 16B-aligned.
#pragma unroll
    for (int q = threadIdx.x; q < 384; q += 256) {
        int b = q / 12;
        int k = q - 12 * b;
        float4 w4;
        int e0 = 4 * k;                     // element index 0..47
        w4.x = so[(e0 + 0) / 3][b][(e0 + 0) % 3];
        w4.y = so[(e0 + 1) / 3][b][(e0 + 1) % 3];
        w4.z = so[(e0 + 2) / 3][b][(e0 + 2) % 3];
        w4.w = so[(e0 + 3) / 3][b][(e0 + 3) % 3];
        *(float4*)&out[((size_t)b * NV + bv0) * 3 + e0] = w4;
    }
}

// ---------------------------------------------------------------------------
extern "C" void kernel_launch(void* const* d_in, const int* in_sizes, int n_in,
                              void* d_out, int out_size)
{
    const float* points = (const float*)d_in[0];  // (BS, 3, V)
    const int*   faces  = (const int*)  d_in[1];  // (F, 3)
    const int*   vti    = (const int*)  d_in[2];  // (V, C)
    const float* vtw    = (const float*)d_in[3];  // (V, C, 1)
    float*       out    = (float*)d_out;          // (BS, V, 3)

    const int smem_bytes = 2 * BUFW * 4;          // 49920 B (> 48KB static)
    static int attr_set = 0;                       // host-side, idempotent
    if (!attr_set) {
        cudaFuncSetAttribute(transpose_kernel,
                             cudaFuncAttributeMaxDynamicSharedMemorySize,
                             smem_bytes);
        attr_set = 1;
    }

    // K1: pipelined transpose, 256 CTAs x 4 tiles.
    transpose_kernel<<<NV / (TV * NTILE), 256, smem_bytes>>>(points);

    // K2, K3: programmatic dependent launches (PDL).
    cudaLaunchAttribute attr[1];
    attr[0].id = cudaLaunchAttributeProgrammaticStreamSerialization;
    attr[0].val.programmaticStreamSerializationAllowed = 1;

    {
        int warps  = NF / 2;                // 65025
        int blocks = (warps + 7) / 8;       // 8 warps per block
        cudaLaunchConfig_t cfg = {};
        cfg.gridDim  = dim3(blocks);
        cfg.blockDim = dim3(256);
        cfg.attrs    = attr;
        cfg.numAttrs = 1;
        cudaLaunchKernelEx(&cfg, face_normals_kernel, faces);
    }
    {
        cudaLaunchConfig_t cfg = {};
        cfg.gridDim  = dim3(NV / 16);       // 4096 blocks, 2 verts/warp
        cfg.blockDim = dim3(256);
        cfg.attrs    = attr;
        cfg.numAttrs = 1;
        cudaLaunchKernelEx(&cfg, vertex_normals_kernel, vti, vtw, out);
    }
}